// round 15
// baseline (speedup 1.0000x reference)
#include <cuda_runtime.h>

// Shapes (fixed by the problem)
#define B_   4
#define N_   128
#define M_   128
#define D_   256
#define BD_  1024
#define R_   (B_ * N_)        // 512 flattened (b,n) rows

// Scratch (no cudaMalloc allowed)
__device__ float g_Aprime[D_ * D_];   // 256 KB: A'[d,e] = sum_k A[d,e,k]*W[k]

// ---------------------------------------------------------------------------
// Kernel 1: A'[row] = dot(A[row, :], W[:]); row = d*256 + e.
// ONE row per warp, linear 268 MB DRAM stream (81% DRAM / 42.3us = the LTS
// cap). FROZEN core. Blocks 0..63 also zero S (256 KB, 0.1% extra traffic)
// so the tail's two e-halves can atomicAdd into it.
// ---------------------------------------------------------------------------
__global__ __launch_bounds__(256) void k1_fold_w(
    const float4* __restrict__ A4,   // [65536 rows][256 float4]
    const float4* __restrict__ W4,   // [256 float4]
    float* __restrict__ Ap,          // [65536]
    float4* __restrict__ S4)         // [16384] = S as float4, zeroed here
{
    if (blockIdx.x < 64)             // zero S: 64 blocks x 256 thr x 16 B
        S4[blockIdx.x * 256 + threadIdx.x] = make_float4(0.f, 0.f, 0.f, 0.f);

    __shared__ float4 ws[BD_ / 4];   // 4 KB
    ws[threadIdx.x] = W4[threadIdx.x];
    __syncthreads();

    int warp = (blockIdx.x * blockDim.x + threadIdx.x) >> 5;   // 0..65535
    int lane = threadIdx.x & 31;
    const float4* row = A4 + (size_t)warp * (BD_ / 4);

    float s = 0.0f;
#pragma unroll
    for (int i = 0; i < 8; ++i) {
        float4 a = __ldcs(&row[lane + i * 32]);
        float4 w = ws[lane + i * 32];
        s += a.x * w.x + a.y * w.y;
        s += a.z * w.z + a.w * w.w;
    }
#pragma unroll
    for (int o = 16; o > 0; o >>= 1)
        s += __shfl_xor_sync(0xFFFFFFFFu, s, o);
    if (lane == 0) Ap[warp] = s;
}

// ---------------------------------------------------------------------------
// Fused tail (PDL secondary): grid (64 rx, 2 e-halves) = 128 blocks,
// 1024 threads. Each block: 8 r-rows (same b), ONE 128-e half.
//  Stage A: partial T[8][128] over its e-half; 8-way d-split (32 d/thread,
//           e in low lane bits -> coalesced), smem reduce over dq.
//  Stage B: partial S[8][128] over its e-half; shuffle-reduce over eo;
//           atomicAdd into k1-zeroed S. Exactly 2 contributors/output; fp32
//           add commutative -> deterministic. Bias folded into eh==0.
// Traffic: A' 16 MB (was 32), Y 8 MB (was 16) -> ~3.8us at the 6.4TB/s L2 cap.
// ---------------------------------------------------------------------------
__global__ __launch_bounds__(1024) void k23_fused(
    const float4* __restrict__ X4,   // [512][64] float4
    const float* __restrict__ Ap,    // [256*256]
    const float4* __restrict__ Y4,   // [512][64] float4
    const float* __restrict__ bias,  // [1]
    float* __restrict__ S)           // [512*128], zeroed by k1
{
    int rx = blockIdx.x;             // 0..63 -> rows rx*8 .. rx*8+7
    int eh = blockIdx.y;             // 0..1
    int r0 = rx * 8;                 // 64*8 = 512 rows total  (R13 bug fixed)
    int b  = r0 >> 7;                // 8 | 128 -> rows never straddle b
    int tid = threadIdx.x;

    __shared__ float4 xs4[8][D_ / 4];   // 8 KB   X tile (full d)
    __shared__ float  ps[8][8][128];    // 32 KB  partials [dq][r][el]
    __shared__ float4 ts4[8][32];       // 4 KB   T half-rows (128 e)
    __shared__ float  sbias;
    float* ts = (float*)ts4;

    // ---- k1-independent prologue (overlaps primary under PDL) ----
    if (tid < 512) {                    // X tile: 8 rows x 64 float4
        int ri = tid >> 6, c = tid & 63;
        xs4[ri][c] = X4[(size_t)(r0 + ri) * (D_ / 4) + c];
    }
    if (tid == 0) sbias = (eh == 0) ? bias[0] : 0.0f;
    if (tid < 512) {   // prefetch this block's Y[b] half-slab (64 KB)
        const char* yb = (const char*)(Y4 + (size_t)b * M_ * (D_ / 4));
        size_t off = (size_t)(tid >> 2) * 1024 + eh * 512 + (tid & 3) * 128;
        asm volatile("prefetch.global.L2 [%0];" :: "l"(yb + off));
    }

    // ---- wait for k1 (programmatic dependency; no-op if launched plainly) --
#if __CUDA_ARCH__ >= 900
    cudaGridDependencySynchronize();
#endif
    __syncthreads();

    // ---- Stage A: T_half[8][128] = X_tile @ A'[:, e-half] ----
    {
        int el = tid & 127;              // LOW bits -> coalesced A' loads
        int dq = tid >> 7;               // 0..7 -> d in [dq*32, dq*32+32)
        const float* ap = Ap + (size_t)(dq * 32) * D_ + eh * 128 + el;

        float acc[8] = {0,0,0,0,0,0,0,0};
#pragma unroll
        for (int i = 0; i < 8; ++i) {    // 8 groups of 4 d, fully unrolled
            int d4 = dq * 8 + i;
            float v0 = ap[(4 * i + 0) * D_];
            float v1 = ap[(4 * i + 1) * D_];
            float v2 = ap[(4 * i + 2) * D_];
            float v3 = ap[(4 * i + 3) * D_];
#pragma unroll
            for (int r = 0; r < 8; ++r) {
                float4 xr = xs4[r][d4];  // warp-uniform LDS.128 broadcast
                acc[r] = fmaf(xr.x, v0, acc[r]);
                acc[r] = fmaf(xr.y, v1, acc[r]);
                acc[r] = fmaf(xr.z, v2, acc[r]);
                acc[r] = fmaf(xr.w, v3, acc[r]);
            }
        }
#pragma unroll
        for (int r = 0; r < 8; ++r)
            ps[dq][r][el] = acc[r];
    }
    __syncthreads();

    // reduce over dq: 1024 outputs; thread -> (r = tid>>7, el = tid&127)
    {
        int r  = tid >> 7;
        int el = tid & 127;
        float s = 0.f;
#pragma unroll
        for (int q = 0; q < 8; ++q) s += ps[q][r][el];
        ts[r * 128 + el] = s;
    }
    __syncthreads();

    // ---- Stage B: partial S over this e-half; atomic combine ----
    {
        int m  = tid >> 3;               // 0..127
        int eo = tid & 7;                // 0..7 (lane bits 0..2)
        const float4* y = Y4 + (size_t)(b * M_ + m) * (D_ / 4) + eh * 32;

        float u[8] = {0,0,0,0,0,0,0,0};
#pragma unroll
        for (int k = 0; k < 4; ++k) {
            int c = eo + 8 * k;          // float4 idx in half, coalesced
            float4 yv = y[c];
#pragma unroll
            for (int r = 0; r < 8; ++r) {
                float4 t = ts4[r][c];
                u[r] = fmaf(t.x, yv.x, u[r]);
                u[r] = fmaf(t.y, yv.y, u[r]);
                u[r] = fmaf(t.z, yv.z, u[r]);
                u[r] = fmaf(t.w, yv.w, u[r]);
            }
        }
#pragma unroll
        for (int o = 4; o > 0; o >>= 1)
#pragma unroll
            for (int r = 0; r < 8; ++r)
                u[r] += __shfl_xor_sync(0xFFFFFFFFu, u[r], o);

        if (eo == 0) {
            float bb = sbias;            // bias only from eh==0 half
#pragma unroll
            for (int r = 0; r < 8; ++r)
                atomicAdd(&S[(size_t)(r0 + r) * M_ + m], u[r] + bb);
        }
    }
}

// ---------------------------------------------------------------------------
extern "C" void kernel_launch(void* const* d_in, const int* in_sizes, int n_in,
                              void* d_out, int out_size)
{
    const float* X  = (const float*)d_in[0];   // [4,128,256]
    const float* Y  = (const float*)d_in[1];   // [4,128,256]
    const float* A  = (const float*)d_in[2];   // [256,256,1024]
    const float* W  = (const float*)d_in[3];   // [1,1024]
    const float* bb = (const float*)d_in[4];   // [1]
    float* S = (float*)d_out;                  // [4,128,128]

    float* Ap;  cudaGetSymbolAddress((void**)&Ap, g_Aprime);

    // K1: 65536 rows, 1 per warp, 8 warps/block -> 8192 blocks (+ S zeroing)
    k1_fold_w<<<(D_ * D_) / 8, 256>>>((const float4*)A, (const float4*)W, Ap,
                                      (float4*)S);

    // Fused tail as PDL secondary: (64 rx * 8 rows, 2 e-halves) = 512 rows.
    cudaLaunchConfig_t cfg = {};
    cfg.gridDim  = dim3(R_ / 8, 2);            // 64 x 2 = 128 blocks, 8 rows each
    cfg.blockDim = dim3(1024);
    cfg.dynamicSmemBytes = 0;
    cfg.stream = 0;
    cudaLaunchAttribute attr[1];
    attr[0].id = cudaLaunchAttributeProgrammaticStreamSerialization;
    attr[0].val.programmaticStreamSerializationAllowed = 1;
    cfg.attrs = attr;
    cfg.numAttrs = 1;

    cudaError_t e = cudaLaunchKernelEx(&cfg, k23_fused,
        (const float4*)X, (const float*)Ap, (const float4*)Y, bb, S);
    if (e != cudaSuccess) {
        dim3 g(R_ / 8, 2);
        k23_fused<<<g, 1024>>>((const float4*)X, Ap, (const float4*)Y, bb, S);
    }
}